// round 14
// baseline (speedup 1.0000x reference)
#include <cuda_runtime.h>
#include <cuda_bf16.h>
#include <math.h>
#include <stdint.h>

// ---------------- problem constants ----------------
constexpr int B_    = 8;
constexpr int S_    = 512;
constexpr int D_    = 1024;
constexpr int H_    = 16;
constexpr int DH_   = 64;
constexpr int NST_  = 32;
constexpr int L_    = 2;
constexpr int VOCAB_= 128;
constexpr int M_    = B_ * S_;   // 4096
constexpr int K_    = D_;        // 1024
constexpr int BKc_  = 32;        // K per stage
constexpr int NS_   = K_ / BKc_; // 32 stages
constexpr int T_    = 64;        // scan chunk length
constexpr int P_    = S_ / T_;   // 8 chunks

// ---------------- scratch (static device globals) ----------------
__device__ float g_x   [M_ * D_];
__device__ float g_qkvg[M_ * 4 * D_];
__device__ float g_st  [B_*H_ * P_ * NST_ * DH_];
__device__ int   g_flags[L_ * B_*H_ * P_];
__device__ float g_bcat[L_ * 4 * D_];
__device__ __nv_bfloat16 g_xn_hi[M_ * D_], g_xn_lo[M_ * D_];
__device__ __nv_bfloat16 g_o_hi [M_ * D_], g_o_lo [M_ * D_];
__device__ __nv_bfloat16 g_wc_hi[L_*4*D_*D_], g_wc_lo[L_*4*D_*D_];
__device__ __nv_bfloat16 g_wo_hi[L_*D_*D_],   g_wo_lo[L_*D_*D_];
__device__ __nv_bfloat16 g_hw_hi[VOCAB_*D_],  g_hw_lo[VOCAB_*D_];

// ---------------- PTX helpers (baseline sm_80-era ISA only) ----------------
__device__ __forceinline__ uint32_t smem_u32(const void* p) {
    uint32_t a;
    asm("{ .reg .u64 t; cvta.to.shared.u64 t, %1; cvt.u32.u64 %0, t; }" : "=r"(a) : "l"(p));
    return a;
}
__device__ __forceinline__ void cp16(uint32_t dst, const void* src) {
    asm volatile("cp.async.cg.shared.global [%0], [%1], 16;" :: "r"(dst), "l"(src));
}
__device__ __forceinline__ void cp_commit() {
    asm volatile("cp.async.commit_group;" ::: "memory");
}
template<int N>
__device__ __forceinline__ void cp_wait() {
    asm volatile("cp.async.wait_group %0;" :: "n"(N) : "memory");
}
__device__ __forceinline__ void ldsm4(uint32_t* r, uint32_t addr) {
    asm volatile("ldmatrix.sync.aligned.m8n8.x4.shared.b16 {%0,%1,%2,%3}, [%4];"
        : "=r"(r[0]), "=r"(r[1]), "=r"(r[2]), "=r"(r[3]) : "r"(addr));
}
__device__ __forceinline__ void mma_bf16(float* c, const uint32_t* a, const uint32_t* b) {
    asm volatile(
        "mma.sync.aligned.m16n8k16.row.col.f32.bf16.bf16.f32 "
        "{%0,%1,%2,%3}, {%4,%5,%6,%7}, {%8,%9}, {%0,%1,%2,%3};"
        : "+f"(c[0]), "+f"(c[1]), "+f"(c[2]), "+f"(c[3])
        : "r"(a[0]), "r"(a[1]), "r"(a[2]), "r"(a[3]), "r"(b[0]), "r"(b[1]));
}
__device__ __forceinline__ void split2(float v, __nv_bfloat16& h, __nv_bfloat16& l) {
    h = __float2bfloat16(v);
    l = __float2bfloat16(v - __bfloat162float(h));
}
__device__ __forceinline__ int ld_acquire(const int* p) {
    int v;
    asm volatile("ld.global.acquire.gpu.b32 %0, [%1];" : "=r"(v) : "l"(p) : "memory");
    return v;
}

// ---------------- fused weight cvt + bias pack + embed + flag zero ----------------
__global__ void __launch_bounds__(256)
cvt_all(const float* __restrict__ wq, const float* __restrict__ wk,
        const float* __restrict__ wv, const float* __restrict__ wg,
        const float* __restrict__ wo, const float* __restrict__ hw,
        const float* __restrict__ bq, const float* __restrict__ bk,
        const float* __restrict__ bv, const float* __restrict__ bg,
        const int* __restrict__ tokens, const float* __restrict__ emb,
        const float* __restrict__ pos,
        __nv_bfloat16* __restrict__ wch, __nv_bfloat16* __restrict__ wcl,
        __nv_bfloat16* __restrict__ woh, __nv_bfloat16* __restrict__ wol,
        __nv_bfloat16* __restrict__ hwh, __nv_bfloat16* __restrict__ hwl,
        float* __restrict__ bcat, float* __restrict__ x, int* __restrict__ flags)
{
    constexpr int PC4 = D_ * D_ / 4;
    constexpr int WC4 = L_ * 4 * PC4;
    constexpr int WO4 = L_ * PC4;
    constexpr int HW4 = VOCAB_ * D_ / 4;
    constexpr int BC4 = L_ * 4 * D_ / 4;
    constexpr int EMB4= M_ * D_ / 4;
    constexpr int FLG = L_ * B_ * H_ * P_;
    int idx = blockIdx.x * 256 + threadIdx.x;
    const float4* src;
    __nv_bfloat16 *dh, *dl;
    int d4;
    if (idx < WC4) {
        int q   = idx >> 18;
        int p   = q & 3;
        int off = idx & (PC4 - 1);
        int l   = q >> 2;
        const float* s = (p == 0) ? wq : (p == 1) ? wk : (p == 2) ? wv : wg;
        src = reinterpret_cast<const float4*>(s) + (size_t)l * PC4 + off;
        dh = wch; dl = wcl; d4 = idx;
    } else if (idx < WC4 + WO4) {
        int j = idx - WC4;
        src = reinterpret_cast<const float4*>(wo) + j;
        dh = woh; dl = wol; d4 = j;
    } else if (idx < WC4 + WO4 + HW4) {
        int j = idx - WC4 - WO4;
        src = reinterpret_cast<const float4*>(hw) + j;
        dh = hwh; dl = hwl; d4 = j;
    } else if (idx < WC4 + WO4 + HW4 + BC4) {
        int j  = idx - WC4 - WO4 - HW4;
        int p4 = j & 255;
        int p  = (j >> 8) & 3;
        int l  = j >> 10;
        const float* s = (p == 0) ? bq : (p == 1) ? bk : (p == 2) ? bv : bg;
        float4 v = reinterpret_cast<const float4*>(s + (size_t)l * D_)[p4];
        reinterpret_cast<float4*>(bcat)[j] = v;
        return;
    } else if (idx < WC4 + WO4 + HW4 + BC4 + EMB4) {
        int j   = idx - WC4 - WO4 - HW4 - BC4;
        int row = j >> 8;
        int c4  = j & 255;
        int s   = row & (S_ - 1);
        int tok = tokens[row];
        float4 e = reinterpret_cast<const float4*>(emb + (size_t)tok * D_)[c4];
        float4 p = reinterpret_cast<const float4*>(pos + (size_t)s   * D_)[c4];
        e.x += p.x; e.y += p.y; e.z += p.z; e.w += p.w;
        reinterpret_cast<float4*>(x)[j] = e;
        return;
    } else if (idx < WC4 + WO4 + HW4 + BC4 + EMB4 + FLG) {
        flags[idx - WC4 - WO4 - HW4 - BC4 - EMB4] = 0;
        return;
    } else return;

    float4 v = *src;
    __nv_bfloat16 h[4], l[4];
    split2(v.x, h[0], l[0]); split2(v.y, h[1], l[1]);
    split2(v.z, h[2], l[2]); split2(v.w, h[3], l[3]);
    reinterpret_cast<uint2*>(dh)[d4] = *reinterpret_cast<uint2*>(h);
    reinterpret_cast<uint2*>(dl)[d4] = *reinterpret_cast<uint2*>(l);
}

// ---------------- layernorm -> bf16 hi/lo ----------------
__global__ void __launch_bounds__(256)
ln_bf16_kernel(const float* __restrict__ x,
               const float* __restrict__ gw,
               const float* __restrict__ bw,
               __nv_bfloat16* __restrict__ yhi,
               __nv_bfloat16* __restrict__ ylo)
{
    int row = blockIdx.x;
    int t   = threadIdx.x;
    float4 xv = reinterpret_cast<const float4*>(x + (size_t)row * D_)[t];

    float s  = xv.x + xv.y + xv.z + xv.w;
    float ss = xv.x*xv.x + xv.y*xv.y + xv.z*xv.z + xv.w*xv.w;
    #pragma unroll
    for (int o = 16; o; o >>= 1) {
        s  += __shfl_xor_sync(0xffffffffu, s,  o);
        ss += __shfl_xor_sync(0xffffffffu, ss, o);
    }
    __shared__ float sh_s[8], sh_ss[8];
    int w = t >> 5;
    if ((t & 31) == 0) { sh_s[w] = s; sh_ss[w] = ss; }
    __syncthreads();
    __shared__ float s_mean, s_inv;
    if (w == 0) {
        s  = (t < 8) ? sh_s[t]  : 0.f;
        ss = (t < 8) ? sh_ss[t] : 0.f;
        #pragma unroll
        for (int o = 4; o; o >>= 1) {
            s  += __shfl_xor_sync(0xffffffffu, s,  o);
            ss += __shfl_xor_sync(0xffffffffu, ss, o);
        }
        if (t == 0) {
            float mean = s * (1.f / D_);
            float var  = ss * (1.f / D_) - mean * mean;
            s_mean = mean;
            s_inv  = rsqrtf(var + 1e-5f);
        }
    }
    __syncthreads();
    float mean = s_mean, inv = s_inv;

    float4 gv = reinterpret_cast<const float4*>(gw)[t];
    float4 bv = reinterpret_cast<const float4*>(bw)[t];
    float o0 = (xv.x - mean) * inv * gv.x + bv.x;
    float o1 = (xv.y - mean) * inv * gv.y + bv.y;
    float o2 = (xv.z - mean) * inv * gv.z + bv.z;
    float o3 = (xv.w - mean) * inv * gv.w + bv.w;

    __nv_bfloat16 h[4], l[4];
    split2(o0, h[0], l[0]); split2(o1, h[1], l[1]);
    split2(o2, h[2], l[2]); split2(o3, h[3], l[3]);
    reinterpret_cast<uint2*>(yhi + (size_t)row * D_)[t] = *reinterpret_cast<uint2*>(h);
    reinterpret_cast<uint2*>(ylo + (size_t)row * D_)[t] = *reinterpret_cast<uint2*>(l);
}

// ---------------- persistent HMMA GEMM: C = A*W^T + bias (+res) ----
// Flattened (tile, stage) pipeline: 3-stage cp.async rotation continues
// across tile boundaries; epilogue (regs->gmem, no smem) overlaps the next
// tile's prefetches. Grid = min(nTiles, 2*SMs).
template<int BM, bool RES>
__global__ void __launch_bounds__(256, 2)
gemm_mma(const __nv_bfloat16* __restrict__ Ahi, const __nv_bfloat16* __restrict__ Alo,
         const __nv_bfloat16* __restrict__ Whi, const __nv_bfloat16* __restrict__ Wlo,
         const float* __restrict__ bias, const float* __restrict__ res,
         float* __restrict__ C, int Nn, int nTilesX, int nTiles)
{
    constexpr int MT    = BM / 32;
    constexpr int ABYTES= BM * 128;
    constexpr int STAGE = (BM + 128) * 128;
    constexpr int NCHNK = (BM + 128) * 8;
    constexpr int PER   = NCHNK / 256;

    extern __shared__ char smem[];
    const uint32_t sb = smem_u32(smem);

    const int tid  = threadIdx.x;
    const int lane = tid & 31;
    const int wid  = tid >> 5;
    const int wm   = wid & 1;
    const int wn   = wid >> 1;

    const int myT = (nTiles - 1 - (int)blockIdx.x) / (int)gridDim.x + 1;
    const int totalIt = myT * NS_;

    // load for flattened iteration it = w*NS_ + s
    auto load_iter = [&](int it) {
        const int w  = it >> 5;           // NS_ = 32
        const int s  = it & 31;
        const int t  = blockIdx.x + w * gridDim.x;
        const int bm = (t / nTilesX) * BM;
        const int bn = (t % nTilesX) * 128;
        const int k0 = s * BKc_;
        const uint32_t base = sb + (uint32_t)((it % 3) * STAGE);
        #pragma unroll
        for (int i = 0; i < PER; i++) {
            const int g   = tid + i * 256;
            const bool isA = (g < BM * 8);
            const int cid = isA ? g : g - BM * 8;
            const int r   = cid >> 3;
            const int c   = cid & 7;
            const uint32_t dst = base +
                (uint32_t)((isA ? 0 : ABYTES) + r * 128 + ((c ^ (r & 7)) * 16));
            const bool hi = (c < 4);
            const int kof = (c & 3) * 8 + k0;
            const __nv_bfloat16* p = isA
                ? (hi ? Ahi : Alo) + (size_t)(bm + r) * K_ + kof
                : (hi ? Whi : Wlo) + (size_t)(bn + r) * K_ + kof;
            cp16(dst, p);
        }
    };

    float acc[MT][4][4];
    #pragma unroll
    for (int i = 0; i < MT; i++)
        #pragma unroll
        for (int j = 0; j < 4; j++)
            #pragma unroll
            for (int q = 0; q < 4; q++) acc[i][j][q] = 0.f;

    const int a_row = wm * (BM / 2) + (lane & 7) + ((lane >> 3) & 1) * 8;
    const int a_chk = (lane >> 4) & 1;
    const int b_row = wn * 32 + (lane & 7) + ((lane >> 4) & 1) * 8;
    const int b_chk = (lane >> 3) & 1;
    const int gid = lane >> 2;
    const int tig = lane & 3;

    load_iter(0); cp_commit();
    if (totalIt > 1) { load_iter(1); cp_commit(); }

    for (int w = 0; w < myT; w++) {
        for (int s = 0; s < NS_; s++) {
            const int it = w * NS_ + s;
            if (it + 1 < totalIt) cp_wait<1>(); else cp_wait<0>();
            __syncthreads();
            if (it + 2 < totalIt) { load_iter(it + 2); cp_commit(); }

            const uint32_t ab = sb + (uint32_t)((it % 3) * STAGE);
            const uint32_t wb = ab + ABYTES;

            #pragma unroll
            for (int kk = 0; kk < 2; kk++) {
                uint32_t ah[MT][4], al[MT][4];
                #pragma unroll
                for (int mt = 0; mt < MT; mt++) {
                    const int row = a_row + mt * 16;
                    const int ch  = kk * 2 + a_chk;
                    ldsm4(ah[mt], ab + row * 128 + (( ch      ^ (row & 7)) * 16));
                    ldsm4(al[mt], ab + row * 128 + (((ch + 4) ^ (row & 7)) * 16));
                }
                #pragma unroll
                for (int np = 0; np < 2; np++) {
                    const int row = b_row + np * 16;
                    const int ch  = kk * 2 + b_chk;
                    uint32_t t0[4], t1[4];
                    ldsm4(t0, wb + row * 128 + (( ch      ^ (row & 7)) * 16));
                    ldsm4(t1, wb + row * 128 + (((ch + 4) ^ (row & 7)) * 16));
                    uint32_t bh[2][2] = {{t0[0], t0[1]}, {t0[2], t0[3]}};
                    uint32_t bl[2][2] = {{t1[0], t1[1]}, {t1[2], t1[3]}};
                    #pragma unroll
                    for (int q = 0; q < 2; q++)
                        #pragma unroll
                        for (int mt = 0; mt < MT; mt++)
                            mma_bf16(acc[mt][np*2+q], ah[mt], bh[q]);
                    #pragma unroll
                    for (int q = 0; q < 2; q++)
                        #pragma unroll
                        for (int mt = 0; mt < MT; mt++)
                            mma_bf16(acc[mt][np*2+q], ah[mt], bl[q]);
                    #pragma unroll
                    for (int q = 0; q < 2; q++)
                        #pragma unroll
                        for (int mt = 0; mt < MT; mt++)
                            mma_bf16(acc[mt][np*2+q], al[mt], bh[q]);
                }
            }
        }

        // ---- epilogue for tile w (regs -> gmem; no smem; overlaps prefetch) ----
        {
            const int t  = blockIdx.x + w * gridDim.x;
            const int bm = (t / nTilesX) * BM;
            const int bn = (t % nTilesX) * 128;
            #pragma unroll
            for (int mt = 0; mt < MT; mt++) {
                const int row0 = bm + wm * (BM / 2) + mt * 16 + gid;
                #pragma unroll
                for (int nt = 0; nt < 4; nt++) {
                    const int col = bn + wn * 32 + nt * 8 + tig * 2;
                    const float bx = bias[col], by = bias[col + 1];
                    float c0 = acc[mt][nt][0] + bx, c1 = acc[mt][nt][1] + by;
                    float c2 = acc[mt][nt][2] + bx, c3 = acc[mt][nt][3] + by;
                    if (RES) {
                        float2 r0 = *reinterpret_cast<const float2*>(&res[(size_t)row0 * Nn + col]);
                        float2 r1 = *reinterpret_cast<const float2*>(&res[(size_t)(row0 + 8) * Nn + col]);
                        c0 += r0.x; c1 += r0.y; c2 += r1.x; c3 += r1.y;
                    }
                    *reinterpret_cast<float2*>(&C[(size_t)row0 * Nn + col])       = make_float2(c0, c1);
                    *reinterpret_cast<float2*>(&C[(size_t)(row0 + 8) * Nn + col]) = make_float2(c2, c3);
                }
            }
            #pragma unroll
            for (int i = 0; i < MT; i++)
                #pragma unroll
                for (int jq = 0; jq < 4; jq++)
                    #pragma unroll
                    for (int q = 0; q < 4; q++) acc[i][jq][q] = 0.f;
        }
    }
}

// ---------------- fused chunked scan with decoupled lookback ----------------
// R13 proven structure: scalar math, single barrier per step.
// launch_bounds(64,8): 8 x 148+ = >=1184 resident >= 1024 blocks -> spin safe.
__global__ void __launch_bounds__(64, 8)
scan_fused(const float* __restrict__ qkvg, const float* __restrict__ alog,
           float* __restrict__ st, int* __restrict__ flags,
           __nv_bfloat16* __restrict__ Ohi, __nv_bfloat16* __restrict__ Olo)
{
    const int bh = blockIdx.x, c = blockIdx.y;
    const int b = bh >> 4, h = bh & 15;
    const int j = threadIdx.x;

    __shared__ float sQ[4][NST_], sK[4][NST_], sV[4][DH_], sG[4][DH_];
    __shared__ float obuf[T_][DH_];
    __shared__ float qbuf[T_][NST_];

    float alpha[NST_];
    #pragma unroll
    for (int i = 0; i < NST_; i++)
        alpha[i] = 1.f / (1.f + expf(-alog[h * NST_ + i]));

    float hst[NST_];
    #pragma unroll
    for (int i = 0; i < NST_; i++) hst[i] = 0.f;

    const int m0 = b * S_ + c * T_;
    const float* rows = qkvg + (size_t)m0 * 4096;
    const int qcol = h * DH_;
    const int kcol = D_ + h * DH_;
    const int vcol = 2 * D_ + h * DH_;
    const int gcol = 3 * D_ + h * DH_;

    auto prefetch1 = [&](int t) {
        const float* row = rows + (size_t)t * 4096;
        const int slot = t & 3;
        if (j < 8)       cp16(smem_u32(&sQ[slot][j * 4]),        row + qcol + j * 4);
        else if (j < 16) cp16(smem_u32(&sK[slot][(j - 8) * 4]),  row + kcol + (j - 8) * 4);
        else if (j < 32) cp16(smem_u32(&sV[slot][(j - 16) * 4]), row + vcol + (j - 16) * 4);
    };
    prefetch1(0); cp_commit();
    prefetch1(1); cp_commit();
    prefetch1(2); cp_commit();

    for (int t = 0; t < T_; t++) {
        if      (t + 2 < T_) cp_wait<2>();
        else if (t + 1 < T_) cp_wait<1>();
        else                 cp_wait<0>();
        __syncthreads();
        if (t + 3 < T_) { prefetch1(t + 3); cp_commit(); }
        const int slot = t & 3;
        const float v = sV[slot][j];
        float o0 = 0.f, o1 = 0.f, o2 = 0.f, o3 = 0.f;
        #pragma unroll
        for (int i = 0; i < NST_; i += 4) {
            hst[i]   = fmaf(alpha[i],   hst[i],   sK[slot][i]   * v); o0 = fmaf(sQ[slot][i],   hst[i],   o0);
            hst[i+1] = fmaf(alpha[i+1], hst[i+1], sK[slot][i+1] * v); o1 = fmaf(sQ[slot][i+1], hst[i+1], o1);
            hst[i+2] = fmaf(alpha[i+2], hst[i+2], sK[slot][i+2] * v); o2 = fmaf(sQ[slot][i+2], hst[i+2], o2);
            hst[i+3] = fmaf(alpha[i+3], hst[i+3], sK[slot][i+3] * v); o3 = fmaf(sQ[slot][i+3], hst[i+3], o3);
        }
        obuf[t][j] = (o0 + o1) + (o2 + o3);
        if (j < NST_) qbuf[t][j] = sQ[slot][j];
    }
    __syncthreads();

    if (c < P_ - 1) {
        float* dst = st + (((size_t)bh * P_ + c) * NST_) * DH_ + j;
        #pragma unroll
        for (int i = 0; i < NST_; i++) dst[i * DH_] = hst[i];
        __threadfence();
        __syncthreads();
        if (j == 0) atomicExch(&flags[bh * P_ + c], 1);
    }

    float Hin[NST_];
    #pragma unroll
    for (int i = 0; i < NST_; i++) Hin[i] = 0.f;
    if (c > 0) {
        float aT[NST_];
        #pragma unroll
        for (int i = 0; i < NST_; i++) {
            float a2 = alpha[i];
            #pragma unroll
            for (int q = 0; q < 6; q++) a2 *= a2;   // alpha^64
            aT[i] = a2;
        }
        for (int d = 0; d < c; d++) {
            const int* fp = &flags[bh * P_ + d];
            while (ld_acquire(fp) == 0) { }
            const float* src = st + (((size_t)bh * P_ + d) * NST_) * DH_ + j;
            #pragma unroll
            for (int i = 0; i < NST_; i++)
                Hin[i] = fmaf(aT[i], Hin[i], src[i * DH_]);
        }
    }

    __nv_bfloat16* oh = Ohi + (size_t)m0 * D_ + h * DH_ + j;
    __nv_bfloat16* ol = Olo + (size_t)m0 * D_ + h * DH_ + j;

    auto prefetch2 = [&](int t) {
        const float* row = rows + (size_t)t * 4096;
        const int slot = t & 3;
        if (j < 16) cp16(smem_u32(&sG[slot][j * 4]), row + gcol + j * 4);
    };
    prefetch2(0); cp_commit();
    prefetch2(1); cp_commit();
    prefetch2(2); cp_commit();

    float hp[NST_];
    #pragma unroll
    for (int i = 0; i < NST_; i++) hp[i] = Hin[i];

    for (int t = 0; t < T_; t++) {
        if      (t + 2 < T_) cp_wait<2>();
        else if (t + 1 < T_) cp_wait<1>();
        else                 cp_wait<0>();
        __syncthreads();
        if (t + 3 < T_) { prefetch2(t + 3); cp_commit(); }
        const int slot = t & 3;
        float c0 = 0.f, c1 = 0.f, c2 = 0.f, c3 = 0.f;
        #pragma unroll
        for (int i = 0; i < NST_; i += 4) {
            hp[i]   *= alpha[i];   c0 = fmaf(qbuf[t][i],   hp[i],   c0);
            hp[i+1] *= alpha[i+1]; c1 = fmaf(qbuf[t][i+1], hp[i+1], c1);
            hp[i+2] *= alpha[i+2]; c2 = fmaf(qbuf[t][i+2], hp[i+2], c2);
            hp[i+3] *= alpha[i+3]; c3 = fmaf(qbuf[t][i+3], hp[i+3], c3);
        }
        const float o = obuf[t][j] + ((c0 + c1) + (c2 + c3));
        const float gg = sG[slot][j];
        const float ov = o * gg / (1.f + expf(-gg));
        __nv_bfloat16 hh, ll;
        split2(ov, hh, ll);
        *oh = hh; *ol = ll;
        oh += D_; ol += D_;
    }
}

// ---------------- launch ----------------
extern "C" void kernel_launch(void* const* d_in, const int* in_sizes, int n_in,
                              void* d_out, int out_size)
{
    const int*   tokens = (const int*)  d_in[0];
    const float* emb    = (const float*)d_in[1];
    const float* pos    = (const float*)d_in[2];
    const float* ln_g   = (const float*)d_in[3];
    const float* ln_b   = (const float*)d_in[4];
    const float* wq     = (const float*)d_in[5];
    const float* bq     = (const float*)d_in[6];
    const float* wk     = (const float*)d_in[7];
    const float* bk     = (const float*)d_in[8];
    const float* wv     = (const float*)d_in[9];
    const float* bv     = (const float*)d_in[10];
    const float* wg     = (const float*)d_in[11];
    const float* bg     = (const float*)d_in[12];
    const float* wo     = (const float*)d_in[13];
    const float* bo     = (const float*)d_in[14];
    const float* alogit = (const float*)d_in[15];
    const float* fn_g   = (const float*)d_in[16];
    const float* fn_b   = (const float*)d_in[17];
    const float* head_w = (const float*)d_in[18];
    const float* head_b = (const float*)d_in[19];
    float*       out    = (float*)d_out;

    float *px, *pqkvg, *pst, *pbcat;
    int* pflags;
    __nv_bfloat16 *pxnh, *pxnl, *poh, *pol;
    __nv_bfloat16 *wch, *wcl, *woh, *wol, *hwh, *hwl;
    cudaGetSymbolAddress((void**)&px,    g_x);
    cudaGetSymbolAddress((void**)&pqkvg, g_qkvg);
    cudaGetSymbolAddress((void**)&pst,   g_st);
    cudaGetSymbolAddress((void**)&pflags,g_flags);
    cudaGetSymbolAddress((void**)&pbcat, g_bcat);
    cudaGetSymbolAddress((void**)&pxnh,  g_xn_hi);
    cudaGetSymbolAddress((void**)&pxnl,  g_xn_lo);
    cudaGetSymbolAddress((void**)&poh,   g_o_hi);
    cudaGetSymbolAddress((void**)&pol,   g_o_lo);
    cudaGetSymbolAddress((void**)&wch,   g_wc_hi); cudaGetSymbolAddress((void**)&wcl, g_wc_lo);
    cudaGetSymbolAddress((void**)&woh,   g_wo_hi); cudaGetSymbolAddress((void**)&wol, g_wo_lo);
    cudaGetSymbolAddress((void**)&hwh,   g_hw_hi); cudaGetSymbolAddress((void**)&hwl, g_hw_lo);

    constexpr int SMEM_128 = 3 * (128 + 128) * 128;   // 98304
    constexpr int SMEM_32  = 3 * (32  + 128) * 128;   // 61440
    cudaFuncSetAttribute((gemm_mma<128, false>), cudaFuncAttributeMaxDynamicSharedMemorySize, SMEM_128);
    cudaFuncSetAttribute((gemm_mma<128, true >), cudaFuncAttributeMaxDynamicSharedMemorySize, SMEM_128);
    cudaFuncSetAttribute((gemm_mma<32,  false>), cudaFuncAttributeMaxDynamicSharedMemorySize, SMEM_32);

    int dev = 0, nsm = 148;
    cudaGetDevice(&dev);
    cudaDeviceGetAttribute(&nsm, cudaDevAttrMultiProcessorCount, dev);
    const int slots = 2 * nsm;

    // launch order: harness prepends 2; ncu -s 5 profiles overall #5 = our #3
    // = the first scan_fused.
    constexpr int CVT_TOT = (L_*4*D_*D_ + L_*D_*D_ + VOCAB_*D_ + L_*4*D_ + M_*D_) / 4
                            + L_ * B_ * H_ * P_;
    cvt_all<<<(CVT_TOT + 255) / 256, 256>>>(wq, wk, wv, wg, wo, head_w,
                                            bq, bk, bv, bg, tokens, emb, pos,
                                            wch, wcl, woh, wol, hwh, hwl,
                                            pbcat, px, pflags);                   // 0

    const int qkvg_tiles = (4 * D_ / 128) * (M_ / 128);   // 1024, nx = 32
    const int wo_tiles   = (D_ / 128) * (M_ / 128);       // 256,  nx = 8
    const int head_tiles = M_ / 32;                       // 128,  nx = 1
    const int qkvg_grid = qkvg_tiles < slots ? qkvg_tiles : slots;
    const int wo_grid   = wo_tiles   < slots ? wo_tiles   : slots;
    const int head_grid = head_tiles < slots ? head_tiles : slots;
    const size_t PIECE = (size_t)D_ * D_;

    for (int l = 0; l < L_; l++) {
        const size_t wOff = (size_t)l * PIECE;
        const float* alog = alogit + (size_t)l * H_ * NST_;

        ln_bf16_kernel<<<M_, 256>>>(px, ln_g + l * D_, ln_b + l * D_, pxnh, pxnl); // 1

        gemm_mma<128, false><<<qkvg_grid, 256, SMEM_128>>>(pxnh, pxnl,             // 2
            wch + (size_t)l * 4 * PIECE, wcl + (size_t)l * 4 * PIECE,
            pbcat + l * 4 * D_, nullptr, pqkvg, 4 * D_, 32, qkvg_tiles);

        scan_fused<<<dim3(B_ * H_, P_), 64>>>(pqkvg, alog, pst,                    // 3 <- profiled
            pflags + l * B_ * H_ * P_, poh, pol);

        gemm_mma<128, true><<<wo_grid, 256, SMEM_128>>>(poh, pol, woh + wOff, wol + wOff,
                                                        bo + l * D_, px, px, D_, 8, wo_tiles);
    }

    ln_bf16_kernel<<<M_, 256>>>(px, fn_g, fn_b, pxnh, pxnl);
    gemm_mma<32, false><<<head_grid, 256, SMEM_32>>>(pxnh, pxnl, hwh, hwl,
                                                     head_b, nullptr, out, VOCAB_, 1, head_tiles);
}

// round 15
// speedup vs baseline: 1.0493x; 1.0493x over previous
#include <cuda_runtime.h>
#include <cuda_bf16.h>
#include <math.h>
#include <stdint.h>

// ---------------- problem constants ----------------
constexpr int B_    = 8;
constexpr int S_    = 512;
constexpr int D_    = 1024;
constexpr int H_    = 16;
constexpr int DH_   = 64;
constexpr int NST_  = 32;
constexpr int L_    = 2;
constexpr int VOCAB_= 128;
constexpr int M_    = B_ * S_;   // 4096
constexpr int K_    = D_;        // 1024
constexpr int BKc_  = 32;        // K per stage
constexpr int NS_   = K_ / BKc_; // 32 stages
constexpr int T_    = 32;        // scan chunk length (was 64)
constexpr int P_    = S_ / T_;   // 16 chunks

// ---------------- scratch (static device globals) ----------------
__device__ float g_x   [M_ * D_];
__device__ float g_qkvg[M_ * 4 * D_];
__device__ float g_st  [B_*H_ * P_ * NST_ * DH_];
__device__ int   g_flags[L_ * B_*H_ * P_];
__device__ float g_bcat[L_ * 4 * D_];
__device__ __nv_bfloat16 g_xn_hi[M_ * D_], g_xn_lo[M_ * D_];
__device__ __nv_bfloat16 g_o_hi [M_ * D_], g_o_lo [M_ * D_];
__device__ __nv_bfloat16 g_wc_hi[L_*4*D_*D_], g_wc_lo[L_*4*D_*D_];
__device__ __nv_bfloat16 g_wo_hi[L_*D_*D_],   g_wo_lo[L_*D_*D_];
__device__ __nv_bfloat16 g_hw_hi[VOCAB_*D_],  g_hw_lo[VOCAB_*D_];

// ---------------- PTX helpers (baseline sm_80-era ISA only) ----------------
__device__ __forceinline__ uint32_t smem_u32(const void* p) {
    uint32_t a;
    asm("{ .reg .u64 t; cvta.to.shared.u64 t, %1; cvt.u32.u64 %0, t; }" : "=r"(a) : "l"(p));
    return a;
}
__device__ __forceinline__ void cp16(uint32_t dst, const void* src) {
    asm volatile("cp.async.cg.shared.global [%0], [%1], 16;" :: "r"(dst), "l"(src));
}
__device__ __forceinline__ void cp_commit() {
    asm volatile("cp.async.commit_group;" ::: "memory");
}
template<int N>
__device__ __forceinline__ void cp_wait() {
    asm volatile("cp.async.wait_group %0;" :: "n"(N) : "memory");
}
__device__ __forceinline__ void ldsm4(uint32_t* r, uint32_t addr) {
    asm volatile("ldmatrix.sync.aligned.m8n8.x4.shared.b16 {%0,%1,%2,%3}, [%4];"
        : "=r"(r[0]), "=r"(r[1]), "=r"(r[2]), "=r"(r[3]) : "r"(addr));
}
__device__ __forceinline__ void mma_bf16(float* c, const uint32_t* a, const uint32_t* b) {
    asm volatile(
        "mma.sync.aligned.m16n8k16.row.col.f32.bf16.bf16.f32 "
        "{%0,%1,%2,%3}, {%4,%5,%6,%7}, {%8,%9}, {%0,%1,%2,%3};"
        : "+f"(c[0]), "+f"(c[1]), "+f"(c[2]), "+f"(c[3])
        : "r"(a[0]), "r"(a[1]), "r"(a[2]), "r"(a[3]), "r"(b[0]), "r"(b[1]));
}
__device__ __forceinline__ void split2(float v, __nv_bfloat16& h, __nv_bfloat16& l) {
    h = __float2bfloat16(v);
    l = __float2bfloat16(v - __bfloat162float(h));
}
__device__ __forceinline__ int ld_acquire(const int* p) {
    int v;
    asm volatile("ld.global.acquire.gpu.b32 %0, [%1];" : "=r"(v) : "l"(p) : "memory");
    return v;
}

// ---------------- fused weight cvt + bias pack + embed + flag zero ----------------
__global__ void __launch_bounds__(256)
cvt_all(const float* __restrict__ wq, const float* __restrict__ wk,
        const float* __restrict__ wv, const float* __restrict__ wg,
        const float* __restrict__ wo, const float* __restrict__ hw,
        const float* __restrict__ bq, const float* __restrict__ bk,
        const float* __restrict__ bv, const float* __restrict__ bg,
        const int* __restrict__ tokens, const float* __restrict__ emb,
        const float* __restrict__ pos,
        __nv_bfloat16* __restrict__ wch, __nv_bfloat16* __restrict__ wcl,
        __nv_bfloat16* __restrict__ woh, __nv_bfloat16* __restrict__ wol,
        __nv_bfloat16* __restrict__ hwh, __nv_bfloat16* __restrict__ hwl,
        float* __restrict__ bcat, float* __restrict__ x, int* __restrict__ flags)
{
    constexpr int PC4 = D_ * D_ / 4;
    constexpr int WC4 = L_ * 4 * PC4;
    constexpr int WO4 = L_ * PC4;
    constexpr int HW4 = VOCAB_ * D_ / 4;
    constexpr int BC4 = L_ * 4 * D_ / 4;
    constexpr int EMB4= M_ * D_ / 4;
    constexpr int FLG = L_ * B_ * H_ * P_;
    int idx = blockIdx.x * 256 + threadIdx.x;
    const float4* src;
    __nv_bfloat16 *dh, *dl;
    int d4;
    if (idx < WC4) {
        int q   = idx >> 18;
        int p   = q & 3;
        int off = idx & (PC4 - 1);
        int l   = q >> 2;
        const float* s = (p == 0) ? wq : (p == 1) ? wk : (p == 2) ? wv : wg;
        src = reinterpret_cast<const float4*>(s) + (size_t)l * PC4 + off;
        dh = wch; dl = wcl; d4 = idx;
    } else if (idx < WC4 + WO4) {
        int j = idx - WC4;
        src = reinterpret_cast<const float4*>(wo) + j;
        dh = woh; dl = wol; d4 = j;
    } else if (idx < WC4 + WO4 + HW4) {
        int j = idx - WC4 - WO4;
        src = reinterpret_cast<const float4*>(hw) + j;
        dh = hwh; dl = hwl; d4 = j;
    } else if (idx < WC4 + WO4 + HW4 + BC4) {
        int j  = idx - WC4 - WO4 - HW4;
        int p4 = j & 255;
        int p  = (j >> 8) & 3;
        int l  = j >> 10;
        const float* s = (p == 0) ? bq : (p == 1) ? bk : (p == 2) ? bv : bg;
        float4 v = reinterpret_cast<const float4*>(s + (size_t)l * D_)[p4];
        reinterpret_cast<float4*>(bcat)[j] = v;
        return;
    } else if (idx < WC4 + WO4 + HW4 + BC4 + EMB4) {
        int j   = idx - WC4 - WO4 - HW4 - BC4;
        int row = j >> 8;
        int c4  = j & 255;
        int s   = row & (S_ - 1);
        int tok = tokens[row];
        float4 e = reinterpret_cast<const float4*>(emb + (size_t)tok * D_)[c4];
        float4 p = reinterpret_cast<const float4*>(pos + (size_t)s   * D_)[c4];
        e.x += p.x; e.y += p.y; e.z += p.z; e.w += p.w;
        reinterpret_cast<float4*>(x)[j] = e;
        return;
    } else if (idx < WC4 + WO4 + HW4 + BC4 + EMB4 + FLG) {
        flags[idx - WC4 - WO4 - HW4 - BC4 - EMB4] = 0;
        return;
    } else return;

    float4 v = *src;
    __nv_bfloat16 h[4], l[4];
    split2(v.x, h[0], l[0]); split2(v.y, h[1], l[1]);
    split2(v.z, h[2], l[2]); split2(v.w, h[3], l[3]);
    reinterpret_cast<uint2*>(dh)[d4] = *reinterpret_cast<uint2*>(h);
    reinterpret_cast<uint2*>(dl)[d4] = *reinterpret_cast<uint2*>(l);
}

// ---------------- layernorm -> bf16 hi/lo ----------------
__global__ void __launch_bounds__(256)
ln_bf16_kernel(const float* __restrict__ x,
               const float* __restrict__ gw,
               const float* __restrict__ bw,
               __nv_bfloat16* __restrict__ yhi,
               __nv_bfloat16* __restrict__ ylo)
{
    int row = blockIdx.x;
    int t   = threadIdx.x;
    float4 xv = reinterpret_cast<const float4*>(x + (size_t)row * D_)[t];

    float s  = xv.x + xv.y + xv.z + xv.w;
    float ss = xv.x*xv.x + xv.y*xv.y + xv.z*xv.z + xv.w*xv.w;
    #pragma unroll
    for (int o = 16; o; o >>= 1) {
        s  += __shfl_xor_sync(0xffffffffu, s,  o);
        ss += __shfl_xor_sync(0xffffffffu, ss, o);
    }
    __shared__ float sh_s[8], sh_ss[8];
    int w = t >> 5;
    if ((t & 31) == 0) { sh_s[w] = s; sh_ss[w] = ss; }
    __syncthreads();
    __shared__ float s_mean, s_inv;
    if (w == 0) {
        s  = (t < 8) ? sh_s[t]  : 0.f;
        ss = (t < 8) ? sh_ss[t] : 0.f;
        #pragma unroll
        for (int o = 4; o; o >>= 1) {
            s  += __shfl_xor_sync(0xffffffffu, s,  o);
            ss += __shfl_xor_sync(0xffffffffu, ss, o);
        }
        if (t == 0) {
            float mean = s * (1.f / D_);
            float var  = ss * (1.f / D_) - mean * mean;
            s_mean = mean;
            s_inv  = rsqrtf(var + 1e-5f);
        }
    }
    __syncthreads();
    float mean = s_mean, inv = s_inv;

    float4 gv = reinterpret_cast<const float4*>(gw)[t];
    float4 bv = reinterpret_cast<const float4*>(bw)[t];
    float o0 = (xv.x - mean) * inv * gv.x + bv.x;
    float o1 = (xv.y - mean) * inv * gv.y + bv.y;
    float o2 = (xv.z - mean) * inv * gv.z + bv.z;
    float o3 = (xv.w - mean) * inv * gv.w + bv.w;

    __nv_bfloat16 h[4], l[4];
    split2(o0, h[0], l[0]); split2(o1, h[1], l[1]);
    split2(o2, h[2], l[2]); split2(o3, h[3], l[3]);
    reinterpret_cast<uint2*>(yhi + (size_t)row * D_)[t] = *reinterpret_cast<uint2*>(h);
    reinterpret_cast<uint2*>(ylo + (size_t)row * D_)[t] = *reinterpret_cast<uint2*>(l);
}

// ---------------- HMMA GEMM: C[m,n] = sum_k A[m,k]*W[n,k] + bias (+res) ----
// R13 proven configuration (non-persistent, 3-stage, 2 CTAs/SM).
template<int BM, bool RES>
__global__ void __launch_bounds__(256, 2)
gemm_mma(const __nv_bfloat16* __restrict__ Ahi, const __nv_bfloat16* __restrict__ Alo,
         const __nv_bfloat16* __restrict__ Whi, const __nv_bfloat16* __restrict__ Wlo,
         const float* __restrict__ bias, const float* __restrict__ res,
         float* __restrict__ C, int Nn)
{
    constexpr int MT    = BM / 32;
    constexpr int ABYTES= BM * 128;
    constexpr int STAGE = (BM + 128) * 128;
    constexpr int NCHNK = (BM + 128) * 8;
    constexpr int PER   = NCHNK / 256;

    extern __shared__ char smem[];
    const uint32_t sb = smem_u32(smem);

    const int tid  = threadIdx.x;
    const int lane = tid & 31;
    const int wid  = tid >> 5;
    const int wm   = wid & 1;
    const int wn   = wid >> 1;
    const int bm   = blockIdx.y * BM;
    const int bn   = blockIdx.x * 128;

    auto load_stage = [&](int s, int k0) {
        const uint32_t base = sb + (uint32_t)((s % 3) * STAGE);
        #pragma unroll
        for (int i = 0; i < PER; i++) {
            const int g   = tid + i * 256;
            const bool isA = (g < BM * 8);
            const int cid = isA ? g : g - BM * 8;
            const int r   = cid >> 3;
            const int c   = cid & 7;
            const uint32_t dst = base +
                (uint32_t)((isA ? 0 : ABYTES) + r * 128 + ((c ^ (r & 7)) * 16));
            const bool hi = (c < 4);
            const int kof = (c & 3) * 8 + k0;
            const __nv_bfloat16* p = isA
                ? (hi ? Ahi : Alo) + (size_t)(bm + r) * K_ + kof
                : (hi ? Whi : Wlo) + (size_t)(bn + r) * K_ + kof;
            cp16(dst, p);
        }
    };

    float acc[MT][4][4];
    #pragma unroll
    for (int i = 0; i < MT; i++)
        #pragma unroll
        for (int j = 0; j < 4; j++)
            #pragma unroll
            for (int q = 0; q < 4; q++) acc[i][j][q] = 0.f;

    const int a_row = wm * (BM / 2) + (lane & 7) + ((lane >> 3) & 1) * 8;
    const int a_chk = (lane >> 4) & 1;
    const int b_row = wn * 32 + (lane & 7) + ((lane >> 4) & 1) * 8;
    const int b_chk = (lane >> 3) & 1;

    load_stage(0, 0);    cp_commit();
    load_stage(1, BKc_); cp_commit();

    for (int s = 0; s < NS_; s++) {
        if (s + 1 < NS_) cp_wait<1>(); else cp_wait<0>();
        __syncthreads();
        if (s + 2 < NS_) { load_stage(s + 2, (s + 2) * BKc_); cp_commit(); }

        const uint32_t ab = sb + (uint32_t)((s % 3) * STAGE);
        const uint32_t wb = ab + ABYTES;

        #pragma unroll
        for (int kk = 0; kk < 2; kk++) {
            uint32_t ah[MT][4], al[MT][4];
            #pragma unroll
            for (int mt = 0; mt < MT; mt++) {
                const int row = a_row + mt * 16;
                const int ch  = kk * 2 + a_chk;
                ldsm4(ah[mt], ab + row * 128 + (( ch      ^ (row & 7)) * 16));
                ldsm4(al[mt], ab + row * 128 + (((ch + 4) ^ (row & 7)) * 16));
            }
            #pragma unroll
            for (int np = 0; np < 2; np++) {
                const int row = b_row + np * 16;
                const int ch  = kk * 2 + b_chk;
                uint32_t t0[4], t1[4];
                ldsm4(t0, wb + row * 128 + (( ch      ^ (row & 7)) * 16));
                ldsm4(t1, wb + row * 128 + (((ch + 4) ^ (row & 7)) * 16));
                uint32_t bh[2][2] = {{t0[0], t0[1]}, {t0[2], t0[3]}};
                uint32_t bl[2][2] = {{t1[0], t1[1]}, {t1[2], t1[3]}};
                #pragma unroll
                for (int q = 0; q < 2; q++)
                    #pragma unroll
                    for (int mt = 0; mt < MT; mt++)
                        mma_bf16(acc[mt][np*2+q], ah[mt], bh[q]);
                #pragma unroll
                for (int q = 0; q < 2; q++)
                    #pragma unroll
                    for (int mt = 0; mt < MT; mt++)
                        mma_bf16(acc[mt][np*2+q], ah[mt], bl[q]);
                #pragma unroll
                for (int q = 0; q < 2; q++)
                    #pragma unroll
                    for (int mt = 0; mt < MT; mt++)
                        mma_bf16(acc[mt][np*2+q], al[mt], bh[q]);
            }
        }
    }

    const int gid = lane >> 2;
    const int tig = lane & 3;
    #pragma unroll
    for (int mt = 0; mt < MT; mt++) {
        const int row0 = bm + wm * (BM / 2) + mt * 16 + gid;
        #pragma unroll
        for (int nt = 0; nt < 4; nt++) {
            const int col = bn + wn * 32 + nt * 8 + tig * 2;
            const float bx = bias[col], by = bias[col + 1];
            float c0 = acc[mt][nt][0] + bx, c1 = acc[mt][nt][1] + by;
            float c2 = acc[mt][nt][2] + bx, c3 = acc[mt][nt][3] + by;
            if (RES) {
                float2 r0 = *reinterpret_cast<const float2*>(&res[(size_t)row0 * Nn + col]);
                float2 r1 = *reinterpret_cast<const float2*>(&res[(size_t)(row0 + 8) * Nn + col]);
                c0 += r0.x; c1 += r0.y; c2 += r1.x; c3 += r1.y;
            }
            *reinterpret_cast<float2*>(&C[(size_t)row0 * Nn + col])       = make_float2(c0, c1);
            *reinterpret_cast<float2*>(&C[(size_t)(row0 + 8) * Nn + col]) = make_float2(c2, c3);
        }
    }
}

// ---------------- fused chunked scan with decoupled lookback ----------------
// T=32, P=16: half the serial chain per block, 2x blocks (2048) for issue
// occupancy. Deadlock-free by the standard decoupled-lookback argument:
// every wait targets a strictly lower linear block id (grid x=bh fastest,
// y=c), and CTAs are dispatched in nondecreasing id order as slots free.
__global__ void __launch_bounds__(64, 8)
scan_fused(const float* __restrict__ qkvg, const float* __restrict__ alog,
           float* __restrict__ st, int* __restrict__ flags,
           __nv_bfloat16* __restrict__ Ohi, __nv_bfloat16* __restrict__ Olo)
{
    const int bh = blockIdx.x, c = blockIdx.y;
    const int b = bh >> 4, h = bh & 15;
    const int j = threadIdx.x;

    __shared__ float sQ[4][NST_], sK[4][NST_], sV[4][DH_], sG[4][DH_];
    __shared__ float obuf[T_][DH_];    // 8KB local outputs
    __shared__ float qbuf[T_][NST_];   // 4KB raw q per step

    float alpha[NST_];
    #pragma unroll
    for (int i = 0; i < NST_; i++)
        alpha[i] = 1.f / (1.f + expf(-alog[h * NST_ + i]));

    float hst[NST_];
    #pragma unroll
    for (int i = 0; i < NST_; i++) hst[i] = 0.f;

    const int m0 = b * S_ + c * T_;
    const float* rows = qkvg + (size_t)m0 * 4096;
    const int qcol = h * DH_;
    const int kcol = D_ + h * DH_;
    const int vcol = 2 * D_ + h * DH_;
    const int gcol = 3 * D_ + h * DH_;

    // ---- pass 1: local scan ----
    auto prefetch1 = [&](int t) {
        const float* row = rows + (size_t)t * 4096;
        const int slot = t & 3;
        if (j < 8)       cp16(smem_u32(&sQ[slot][j * 4]),        row + qcol + j * 4);
        else if (j < 16) cp16(smem_u32(&sK[slot][(j - 8) * 4]),  row + kcol + (j - 8) * 4);
        else if (j < 32) cp16(smem_u32(&sV[slot][(j - 16) * 4]), row + vcol + (j - 16) * 4);
    };
    prefetch1(0); cp_commit();
    prefetch1(1); cp_commit();
    prefetch1(2); cp_commit();

    for (int t = 0; t < T_; t++) {
        if      (t + 2 < T_) cp_wait<2>();
        else if (t + 1 < T_) cp_wait<1>();
        else                 cp_wait<0>();
        __syncthreads();
        if (t + 3 < T_) { prefetch1(t + 3); cp_commit(); }
        const int slot = t & 3;
        const float v = sV[slot][j];
        float o0 = 0.f, o1 = 0.f, o2 = 0.f, o3 = 0.f;
        #pragma unroll
        for (int i = 0; i < NST_; i += 4) {
            hst[i]   = fmaf(alpha[i],   hst[i],   sK[slot][i]   * v); o0 = fmaf(sQ[slot][i],   hst[i],   o0);
            hst[i+1] = fmaf(alpha[i+1], hst[i+1], sK[slot][i+1] * v); o1 = fmaf(sQ[slot][i+1], hst[i+1], o1);
            hst[i+2] = fmaf(alpha[i+2], hst[i+2], sK[slot][i+2] * v); o2 = fmaf(sQ[slot][i+2], hst[i+2], o2);
            hst[i+3] = fmaf(alpha[i+3], hst[i+3], sK[slot][i+3] * v); o3 = fmaf(sQ[slot][i+3], hst[i+3], o3);
        }
        obuf[t][j] = (o0 + o1) + (o2 + o3);
        if (j < NST_) qbuf[t][j] = sQ[slot][j];
    }
    __syncthreads();

    // ---- publish local end state (not needed for last chunk) ----
    if (c < P_ - 1) {
        float* dst = st + (((size_t)bh * P_ + c) * NST_) * DH_ + j;
        #pragma unroll
        for (int i = 0; i < NST_; i++) dst[i * DH_] = hst[i];
        __threadfence();
        __syncthreads();
        if (j == 0) atomicExch(&flags[bh * P_ + c], 1);
    }

    // ---- lookback: Hin = sum_d aT^(c-1-d) * st_d ----
    float Hin[NST_];
    #pragma unroll
    for (int i = 0; i < NST_; i++) Hin[i] = 0.f;
    if (c > 0) {
        float aT[NST_];
        #pragma unroll
        for (int i = 0; i < NST_; i++) {
            float a2 = alpha[i];
            #pragma unroll
            for (int q = 0; q < 5; q++) a2 *= a2;   // alpha^32 (T=32)
            aT[i] = a2;
        }
        for (int d = 0; d < c; d++) {
            const int* fp = &flags[bh * P_ + d];
            while (ld_acquire(fp) == 0) { }
            const float* src = st + (((size_t)bh * P_ + d) * NST_) * DH_ + j;
            #pragma unroll
            for (int i = 0; i < NST_; i++)
                Hin[i] = fmaf(aT[i], Hin[i], src[i * DH_]);
        }
    }

    // ---- pass 2: propagate Hin, correct, gate, write ----
    __nv_bfloat16* oh = Ohi + (size_t)m0 * D_ + h * DH_ + j;
    __nv_bfloat16* ol = Olo + (size_t)m0 * D_ + h * DH_ + j;

    auto prefetch2 = [&](int t) {
        const float* row = rows + (size_t)t * 4096;
        const int slot = t & 3;
        if (j < 16) cp16(smem_u32(&sG[slot][j * 4]), row + gcol + j * 4);
    };
    prefetch2(0); cp_commit();
    prefetch2(1); cp_commit();
    prefetch2(2); cp_commit();

    float hp[NST_];
    #pragma unroll
    for (int i = 0; i < NST_; i++) hp[i] = Hin[i];

    for (int t = 0; t < T_; t++) {
        if      (t + 2 < T_) cp_wait<2>();
        else if (t + 1 < T_) cp_wait<1>();
        else                 cp_wait<0>();
        __syncthreads();
        if (t + 3 < T_) { prefetch2(t + 3); cp_commit(); }
        const int slot = t & 3;
        float c0 = 0.f, c1 = 0.f, c2 = 0.f, c3 = 0.f;
        #pragma unroll
        for (int i = 0; i < NST_; i += 4) {
            hp[i]   *= alpha[i];   c0 = fmaf(qbuf[t][i],   hp[i],   c0);
            hp[i+1] *= alpha[i+1]; c1 = fmaf(qbuf[t][i+1], hp[i+1], c1);
            hp[i+2] *= alpha[i+2]; c2 = fmaf(qbuf[t][i+2], hp[i+2], c2);
            hp[i+3] *= alpha[i+3]; c3 = fmaf(qbuf[t][i+3], hp[i+3], c3);
        }
        const float o = obuf[t][j] + ((c0 + c1) + (c2 + c3));
        const float gg = sG[slot][j];
        const float ov = o * gg / (1.f + expf(-gg));
        __nv_bfloat16 hh, ll;
        split2(ov, hh, ll);
        *oh = hh; *ol = ll;
        oh += D_; ol += D_;
    }
}

// ---------------- launch ----------------
extern "C" void kernel_launch(void* const* d_in, const int* in_sizes, int n_in,
                              void* d_out, int out_size)
{
    const int*   tokens = (const int*)  d_in[0];
    const float* emb    = (const float*)d_in[1];
    const float* pos    = (const float*)d_in[2];
    const float* ln_g   = (const float*)d_in[3];
    const float* ln_b   = (const float*)d_in[4];
    const float* wq     = (const float*)d_in[5];
    const float* bq     = (const float*)d_in[6];
    const float* wk     = (const float*)d_in[7];
    const float* bk     = (const float*)d_in[8];
    const float* wv     = (const float*)d_in[9];
    const float* bv     = (const float*)d_in[10];
    const float* wg     = (const float*)d_in[11];
    const float* bg     = (const float*)d_in[12];
    const float* wo     = (const float*)d_in[13];
    const float* bo     = (const float*)d_in[14];
    const float* alogit = (const float*)d_in[15];
    const float* fn_g   = (const float*)d_in[16];
    const float* fn_b   = (const float*)d_in[17];
    const float* head_w = (const float*)d_in[18];
    const float* head_b = (const float*)d_in[19];
    float*       out    = (float*)d_out;

    float *px, *pqkvg, *pst, *pbcat;
    int* pflags;
    __nv_bfloat16 *pxnh, *pxnl, *poh, *pol;
    __nv_bfloat16 *wch, *wcl, *woh, *wol, *hwh, *hwl;
    cudaGetSymbolAddress((void**)&px,    g_x);
    cudaGetSymbolAddress((void**)&pqkvg, g_qkvg);
    cudaGetSymbolAddress((void**)&pst,   g_st);
    cudaGetSymbolAddress((void**)&pflags,g_flags);
    cudaGetSymbolAddress((void**)&pbcat, g_bcat);
    cudaGetSymbolAddress((void**)&pxnh,  g_xn_hi);
    cudaGetSymbolAddress((void**)&pxnl,  g_xn_lo);
    cudaGetSymbolAddress((void**)&poh,   g_o_hi);
    cudaGetSymbolAddress((void**)&pol,   g_o_lo);
    cudaGetSymbolAddress((void**)&wch,   g_wc_hi); cudaGetSymbolAddress((void**)&wcl, g_wc_lo);
    cudaGetSymbolAddress((void**)&woh,   g_wo_hi); cudaGetSymbolAddress((void**)&wol, g_wo_lo);
    cudaGetSymbolAddress((void**)&hwh,   g_hw_hi); cudaGetSymbolAddress((void**)&hwl, g_hw_lo);

    constexpr int SMEM_128 = 3 * (128 + 128) * 128;   // 98304
    constexpr int SMEM_32  = 3 * (32  + 128) * 128;   // 61440
    cudaFuncSetAttribute((gemm_mma<128, false>), cudaFuncAttributeMaxDynamicSharedMemorySize, SMEM_128);
    cudaFuncSetAttribute((gemm_mma<128, true >), cudaFuncAttributeMaxDynamicSharedMemorySize, SMEM_128);
    cudaFuncSetAttribute((gemm_mma<32,  false>), cudaFuncAttributeMaxDynamicSharedMemorySize, SMEM_32);

    // launch order: harness prepends 2; ncu -s 5 profiles overall #5 = our #3
    // = the first scan_fused.
    constexpr int CVT_TOT = (L_*4*D_*D_ + L_*D_*D_ + VOCAB_*D_ + L_*4*D_ + M_*D_) / 4
                            + L_ * B_ * H_ * P_;
    cvt_all<<<(CVT_TOT + 255) / 256, 256>>>(wq, wk, wv, wg, wo, head_w,
                                            bq, bk, bv, bg, tokens, emb, pos,
                                            wch, wcl, woh, wol, hwh, hwl,
                                            pbcat, px, pflags);                   // 0

    const dim3 qkvg_grid(4 * D_ / 128, M_ / 128);   // (32, 32) = 1024 CTAs
    const dim3 wo_grid(D_ / 128, M_ / 128);         // (8, 32)  = 256 CTAs
    const dim3 head_grid(1, M_ / 32);               // (1, 128) = 128 CTAs
    const size_t PIECE = (size_t)D_ * D_;

    for (int l = 0; l < L_; l++) {
        const size_t wOff = (size_t)l * PIECE;
        const float* alog = alogit + (size_t)l * H_ * NST_;

        ln_bf16_kernel<<<M_, 256>>>(px, ln_g + l * D_, ln_b + l * D_, pxnh, pxnl); // 1

        gemm_mma<128, false><<<qkvg_grid, 256, SMEM_128>>>(pxnh, pxnl,             // 2
            wch + (size_t)l * 4 * PIECE, wcl + (size_t)l * 4 * PIECE,
            pbcat + l * 4 * D_, nullptr, pqkvg, 4 * D_);

        scan_fused<<<dim3(B_ * H_, P_), 64>>>(pqkvg, alog, pst,                    // 3 <- profiled
            pflags + l * B_ * H_ * P_, poh, pol);

        gemm_mma<128, true><<<wo_grid, 256, SMEM_128>>>(poh, pol, woh + wOff, wol + wOff,
                                                        bo + l * D_, px, px, D_);
    }

    ln_bf16_kernel<<<M_, 256>>>(px, fn_g, fn_b, pxnh, pxnl);
    gemm_mma<32, false><<<head_grid, 256, SMEM_32>>>(pxnh, pxnl, hwh, hwl,
                                                     head_b, nullptr, out, VOCAB_);
}

// round 16
// speedup vs baseline: 1.0817x; 1.0308x over previous
#include <cuda_runtime.h>
#include <cuda_bf16.h>
#include <math.h>
#include <stdint.h>

// ---------------- problem constants ----------------
constexpr int B_    = 8;
constexpr int S_    = 512;
constexpr int D_    = 1024;
constexpr int H_    = 16;
constexpr int DH_   = 64;
constexpr int NST_  = 32;
constexpr int L_    = 2;
constexpr int VOCAB_= 128;
constexpr int M_    = B_ * S_;   // 4096
constexpr int K_    = D_;        // 1024
constexpr int BKc_  = 32;        // K per stage
constexpr int NS_   = K_ / BKc_; // 32 stages
constexpr int T_    = 64;        // scan chunk length
constexpr int P_    = S_ / T_;   // 8 chunks

// ---------------- scratch (static device globals) ----------------
__device__ float g_x   [M_ * D_];
__device__ float g_qkvg[M_ * 4 * D_];
__device__ float g_st  [B_*H_ * P_ * NST_ * DH_];
__device__ int   g_flags[L_ * B_*H_ * P_];
__device__ float g_bcat[L_ * 4 * D_];
__device__ __nv_bfloat16 g_xn_hi[M_ * D_], g_xn_lo[M_ * D_];
__device__ __nv_bfloat16 g_o_hi [M_ * D_], g_o_lo [M_ * D_];
__device__ __nv_bfloat16 g_wc_hi[L_*4*D_*D_], g_wc_lo[L_*4*D_*D_];
__device__ __nv_bfloat16 g_wo_hi[L_*D_*D_],   g_wo_lo[L_*D_*D_];
__device__ __nv_bfloat16 g_hw_hi[VOCAB_*D_],  g_hw_lo[VOCAB_*D_];

// ---------------- PTX helpers (baseline sm_80-era ISA only) ----------------
__device__ __forceinline__ uint32_t smem_u32(const void* p) {
    uint32_t a;
    asm("{ .reg .u64 t; cvta.to.shared.u64 t, %1; cvt.u32.u64 %0, t; }" : "=r"(a) : "l"(p));
    return a;
}
__device__ __forceinline__ void cp16(uint32_t dst, const void* src) {
    asm volatile("cp.async.cg.shared.global [%0], [%1], 16;" :: "r"(dst), "l"(src));
}
__device__ __forceinline__ void cp_commit() {
    asm volatile("cp.async.commit_group;" ::: "memory");
}
template<int N>
__device__ __forceinline__ void cp_wait() {
    asm volatile("cp.async.wait_group %0;" :: "n"(N) : "memory");
}
__device__ __forceinline__ void ldsm4(uint32_t* r, uint32_t addr) {
    asm volatile("ldmatrix.sync.aligned.m8n8.x4.shared.b16 {%0,%1,%2,%3}, [%4];"
        : "=r"(r[0]), "=r"(r[1]), "=r"(r[2]), "=r"(r[3]) : "r"(addr));
}
__device__ __forceinline__ void mma_bf16(float* c, const uint32_t* a, const uint32_t* b) {
    asm volatile(
        "mma.sync.aligned.m16n8k16.row.col.f32.bf16.bf16.f32 "
        "{%0,%1,%2,%3}, {%4,%5,%6,%7}, {%8,%9}, {%0,%1,%2,%3};"
        : "+f"(c[0]), "+f"(c[1]), "+f"(c[2]), "+f"(c[3])
        : "r"(a[0]), "r"(a[1]), "r"(a[2]), "r"(a[3]), "r"(b[0]), "r"(b[1]));
}
__device__ __forceinline__ void split2(float v, __nv_bfloat16& h, __nv_bfloat16& l) {
    h = __float2bfloat16(v);
    l = __float2bfloat16(v - __bfloat162float(h));
}
__device__ __forceinline__ int ld_acquire(const int* p) {
    int v;
    asm volatile("ld.global.acquire.gpu.b32 %0, [%1];" : "=r"(v) : "l"(p) : "memory");
    return v;
}

// ---------------- fused weight cvt + bias pack + embed + flag zero ----------------
__global__ void __launch_bounds__(256)
cvt_all(const float* __restrict__ wq, const float* __restrict__ wk,
        const float* __restrict__ wv, const float* __restrict__ wg,
        const float* __restrict__ wo, const float* __restrict__ hw,
        const float* __restrict__ bq, const float* __restrict__ bk,
        const float* __restrict__ bv, const float* __restrict__ bg,
        const int* __restrict__ tokens, const float* __restrict__ emb,
        const float* __restrict__ pos,
        __nv_bfloat16* __restrict__ wch, __nv_bfloat16* __restrict__ wcl,
        __nv_bfloat16* __restrict__ woh, __nv_bfloat16* __restrict__ wol,
        __nv_bfloat16* __restrict__ hwh, __nv_bfloat16* __restrict__ hwl,
        float* __restrict__ bcat, float* __restrict__ x, int* __restrict__ flags)
{
    constexpr int PC4 = D_ * D_ / 4;
    constexpr int WC4 = L_ * 4 * PC4;
    constexpr int WO4 = L_ * PC4;
    constexpr int HW4 = VOCAB_ * D_ / 4;
    constexpr int BC4 = L_ * 4 * D_ / 4;
    constexpr int EMB4= M_ * D_ / 4;
    constexpr int FLG = L_ * B_ * H_ * P_;
    int idx = blockIdx.x * 256 + threadIdx.x;
    const float4* src;
    __nv_bfloat16 *dh, *dl;
    int d4;
    if (idx < WC4) {
        int q   = idx >> 18;
        int p   = q & 3;
        int off = idx & (PC4 - 1);
        int l   = q >> 2;
        const float* s = (p == 0) ? wq : (p == 1) ? wk : (p == 2) ? wv : wg;
        src = reinterpret_cast<const float4*>(s) + (size_t)l * PC4 + off;
        dh = wch; dl = wcl; d4 = idx;
    } else if (idx < WC4 + WO4) {
        int j = idx - WC4;
        src = reinterpret_cast<const float4*>(wo) + j;
        dh = woh; dl = wol; d4 = j;
    } else if (idx < WC4 + WO4 + HW4) {
        int j = idx - WC4 - WO4;
        src = reinterpret_cast<const float4*>(hw) + j;
        dh = hwh; dl = hwl; d4 = j;
    } else if (idx < WC4 + WO4 + HW4 + BC4) {
        int j  = idx - WC4 - WO4 - HW4;
        int p4 = j & 255;
        int p  = (j >> 8) & 3;
        int l  = j >> 10;
        const float* s = (p == 0) ? bq : (p == 1) ? bk : (p == 2) ? bv : bg;
        float4 v = reinterpret_cast<const float4*>(s + (size_t)l * D_)[p4];
        reinterpret_cast<float4*>(bcat)[j] = v;
        return;
    } else if (idx < WC4 + WO4 + HW4 + BC4 + EMB4) {
        int j   = idx - WC4 - WO4 - HW4 - BC4;
        int row = j >> 8;
        int c4  = j & 255;
        int s   = row & (S_ - 1);
        int tok = tokens[row];
        float4 e = reinterpret_cast<const float4*>(emb + (size_t)tok * D_)[c4];
        float4 p = reinterpret_cast<const float4*>(pos + (size_t)s   * D_)[c4];
        e.x += p.x; e.y += p.y; e.z += p.z; e.w += p.w;
        reinterpret_cast<float4*>(x)[j] = e;
        return;
    } else if (idx < WC4 + WO4 + HW4 + BC4 + EMB4 + FLG) {
        flags[idx - WC4 - WO4 - HW4 - BC4 - EMB4] = 0;
        return;
    } else return;

    float4 v = *src;
    __nv_bfloat16 h[4], l[4];
    split2(v.x, h[0], l[0]); split2(v.y, h[1], l[1]);
    split2(v.z, h[2], l[2]); split2(v.w, h[3], l[3]);
    reinterpret_cast<uint2*>(dh)[d4] = *reinterpret_cast<uint2*>(h);
    reinterpret_cast<uint2*>(dl)[d4] = *reinterpret_cast<uint2*>(l);
}

// ---------------- layernorm -> bf16 hi/lo ----------------
__global__ void __launch_bounds__(256)
ln_bf16_kernel(const float* __restrict__ x,
               const float* __restrict__ gw,
               const float* __restrict__ bw,
               __nv_bfloat16* __restrict__ yhi,
               __nv_bfloat16* __restrict__ ylo)
{
    int row = blockIdx.x;
    int t   = threadIdx.x;
    float4 xv = reinterpret_cast<const float4*>(x + (size_t)row * D_)[t];

    float s  = xv.x + xv.y + xv.z + xv.w;
    float ss = xv.x*xv.x + xv.y*xv.y + xv.z*xv.z + xv.w*xv.w;
    #pragma unroll
    for (int o = 16; o; o >>= 1) {
        s  += __shfl_xor_sync(0xffffffffu, s,  o);
        ss += __shfl_xor_sync(0xffffffffu, ss, o);
    }
    __shared__ float sh_s[8], sh_ss[8];
    int w = t >> 5;
    if ((t & 31) == 0) { sh_s[w] = s; sh_ss[w] = ss; }
    __syncthreads();
    __shared__ float s_mean, s_inv;
    if (w == 0) {
        s  = (t < 8) ? sh_s[t]  : 0.f;
        ss = (t < 8) ? sh_ss[t] : 0.f;
        #pragma unroll
        for (int o = 4; o; o >>= 1) {
            s  += __shfl_xor_sync(0xffffffffu, s,  o);
            ss += __shfl_xor_sync(0xffffffffu, ss, o);
        }
        if (t == 0) {
            float mean = s * (1.f / D_);
            float var  = ss * (1.f / D_) - mean * mean;
            s_mean = mean;
            s_inv  = rsqrtf(var + 1e-5f);
        }
    }
    __syncthreads();
    float mean = s_mean, inv = s_inv;

    float4 gv = reinterpret_cast<const float4*>(gw)[t];
    float4 bv = reinterpret_cast<const float4*>(bw)[t];
    float o0 = (xv.x - mean) * inv * gv.x + bv.x;
    float o1 = (xv.y - mean) * inv * gv.y + bv.y;
    float o2 = (xv.z - mean) * inv * gv.z + bv.z;
    float o3 = (xv.w - mean) * inv * gv.w + bv.w;

    __nv_bfloat16 h[4], l[4];
    split2(o0, h[0], l[0]); split2(o1, h[1], l[1]);
    split2(o2, h[2], l[2]); split2(o3, h[3], l[3]);
    reinterpret_cast<uint2*>(yhi + (size_t)row * D_)[t] = *reinterpret_cast<uint2*>(h);
    reinterpret_cast<uint2*>(ylo + (size_t)row * D_)[t] = *reinterpret_cast<uint2*>(l);
}

// ---------------- HMMA GEMM: C[m,n] = sum_k A[m,k]*W[n,k] + bias (+res) ----
// R13 proven configuration (non-persistent, 3-stage, 2 CTAs/SM).
template<int BM, bool RES>
__global__ void __launch_bounds__(256, 2)
gemm_mma(const __nv_bfloat16* __restrict__ Ahi, const __nv_bfloat16* __restrict__ Alo,
         const __nv_bfloat16* __restrict__ Whi, const __nv_bfloat16* __restrict__ Wlo,
         const float* __restrict__ bias, const float* __restrict__ res,
         float* __restrict__ C, int Nn)
{
    constexpr int MT    = BM / 32;
    constexpr int ABYTES= BM * 128;
    constexpr int STAGE = (BM + 128) * 128;
    constexpr int NCHNK = (BM + 128) * 8;
    constexpr int PER   = NCHNK / 256;

    extern __shared__ char smem[];
    const uint32_t sb = smem_u32(smem);

    const int tid  = threadIdx.x;
    const int lane = tid & 31;
    const int wid  = tid >> 5;
    const int wm   = wid & 1;
    const int wn   = wid >> 1;
    const int bm   = blockIdx.y * BM;
    const int bn   = blockIdx.x * 128;

    auto load_stage = [&](int s, int k0) {
        const uint32_t base = sb + (uint32_t)((s % 3) * STAGE);
        #pragma unroll
        for (int i = 0; i < PER; i++) {
            const int g   = tid + i * 256;
            const bool isA = (g < BM * 8);
            const int cid = isA ? g : g - BM * 8;
            const int r   = cid >> 3;
            const int c   = cid & 7;
            const uint32_t dst = base +
                (uint32_t)((isA ? 0 : ABYTES) + r * 128 + ((c ^ (r & 7)) * 16));
            const bool hi = (c < 4);
            const int kof = (c & 3) * 8 + k0;
            const __nv_bfloat16* p = isA
                ? (hi ? Ahi : Alo) + (size_t)(bm + r) * K_ + kof
                : (hi ? Whi : Wlo) + (size_t)(bn + r) * K_ + kof;
            cp16(dst, p);
        }
    };

    float acc[MT][4][4];
    #pragma unroll
    for (int i = 0; i < MT; i++)
        #pragma unroll
        for (int j = 0; j < 4; j++)
            #pragma unroll
            for (int q = 0; q < 4; q++) acc[i][j][q] = 0.f;

    const int a_row = wm * (BM / 2) + (lane & 7) + ((lane >> 3) & 1) * 8;
    const int a_chk = (lane >> 4) & 1;
    const int b_row = wn * 32 + (lane & 7) + ((lane >> 4) & 1) * 8;
    const int b_chk = (lane >> 3) & 1;

    load_stage(0, 0);    cp_commit();
    load_stage(1, BKc_); cp_commit();

    for (int s = 0; s < NS_; s++) {
        if (s + 1 < NS_) cp_wait<1>(); else cp_wait<0>();
        __syncthreads();
        if (s + 2 < NS_) { load_stage(s + 2, (s + 2) * BKc_); cp_commit(); }

        const uint32_t ab = sb + (uint32_t)((s % 3) * STAGE);
        const uint32_t wb = ab + ABYTES;

        #pragma unroll
        for (int kk = 0; kk < 2; kk++) {
            uint32_t ah[MT][4], al[MT][4];
            #pragma unroll
            for (int mt = 0; mt < MT; mt++) {
                const int row = a_row + mt * 16;
                const int ch  = kk * 2 + a_chk;
                ldsm4(ah[mt], ab + row * 128 + (( ch      ^ (row & 7)) * 16));
                ldsm4(al[mt], ab + row * 128 + (((ch + 4) ^ (row & 7)) * 16));
            }
            #pragma unroll
            for (int np = 0; np < 2; np++) {
                const int row = b_row + np * 16;
                const int ch  = kk * 2 + b_chk;
                uint32_t t0[4], t1[4];
                ldsm4(t0, wb + row * 128 + (( ch      ^ (row & 7)) * 16));
                ldsm4(t1, wb + row * 128 + (((ch + 4) ^ (row & 7)) * 16));
                uint32_t bh[2][2] = {{t0[0], t0[1]}, {t0[2], t0[3]}};
                uint32_t bl[2][2] = {{t1[0], t1[1]}, {t1[2], t1[3]}};
                #pragma unroll
                for (int q = 0; q < 2; q++)
                    #pragma unroll
                    for (int mt = 0; mt < MT; mt++)
                        mma_bf16(acc[mt][np*2+q], ah[mt], bh[q]);
                #pragma unroll
                for (int q = 0; q < 2; q++)
                    #pragma unroll
                    for (int mt = 0; mt < MT; mt++)
                        mma_bf16(acc[mt][np*2+q], ah[mt], bl[q]);
                #pragma unroll
                for (int q = 0; q < 2; q++)
                    #pragma unroll
                    for (int mt = 0; mt < MT; mt++)
                        mma_bf16(acc[mt][np*2+q], al[mt], bh[q]);
            }
        }
    }

    const int gid = lane >> 2;
    const int tig = lane & 3;
    #pragma unroll
    for (int mt = 0; mt < MT; mt++) {
        const int row0 = bm + wm * (BM / 2) + mt * 16 + gid;
        #pragma unroll
        for (int nt = 0; nt < 4; nt++) {
            const int col = bn + wn * 32 + nt * 8 + tig * 2;
            const float bx = bias[col], by = bias[col + 1];
            float c0 = acc[mt][nt][0] + bx, c1 = acc[mt][nt][1] + by;
            float c2 = acc[mt][nt][2] + bx, c3 = acc[mt][nt][3] + by;
            if (RES) {
                float2 r0 = *reinterpret_cast<const float2*>(&res[(size_t)row0 * Nn + col]);
                float2 r1 = *reinterpret_cast<const float2*>(&res[(size_t)(row0 + 8) * Nn + col]);
                c0 += r0.x; c1 += r0.y; c2 += r1.x; c3 += r1.y;
            }
            *reinterpret_cast<float2*>(&C[(size_t)row0 * Nn + col])       = make_float2(c0, c1);
            *reinterpret_cast<float2*>(&C[(size_t)(row0 + 8) * Nn + col]) = make_float2(c2, c3);
        }
    }
}

// ---------------- fused chunked scan with decoupled lookback ----------------
// R13 proven structure (T=64, scalar math, single barrier per step), plus:
// - pass-2 G prefetches issued BEFORE the lookback (independent loads)
// - c==0 blocks skip the pass-2 correction loop (Hin == 0)
// launch_bounds(64,8): 8 x 148 = 1184 resident >= 1024 blocks -> spin safe.
__global__ void __launch_bounds__(64, 8)
scan_fused(const float* __restrict__ qkvg, const float* __restrict__ alog,
           float* __restrict__ st, int* __restrict__ flags,
           __nv_bfloat16* __restrict__ Ohi, __nv_bfloat16* __restrict__ Olo)
{
    const int bh = blockIdx.x, c = blockIdx.y;
    const int b = bh >> 4, h = bh & 15;
    const int j = threadIdx.x;

    __shared__ float sQ[4][NST_], sK[4][NST_], sV[4][DH_], sG[4][DH_];
    __shared__ float obuf[T_][DH_];    // 16KB local outputs
    __shared__ float qbuf[T_][NST_];   // 8KB  raw q per step

    float alpha[NST_];
    #pragma unroll
    for (int i = 0; i < NST_; i++)
        alpha[i] = 1.f / (1.f + expf(-alog[h * NST_ + i]));

    float hst[NST_];
    #pragma unroll
    for (int i = 0; i < NST_; i++) hst[i] = 0.f;

    const int m0 = b * S_ + c * T_;
    const float* rows = qkvg + (size_t)m0 * 4096;
    const int qcol = h * DH_;
    const int kcol = D_ + h * DH_;
    const int vcol = 2 * D_ + h * DH_;
    const int gcol = 3 * D_ + h * DH_;

    // ---- pass 1: local scan ----
    auto prefetch1 = [&](int t) {
        const float* row = rows + (size_t)t * 4096;
        const int slot = t & 3;
        if (j < 8)       cp16(smem_u32(&sQ[slot][j * 4]),        row + qcol + j * 4);
        else if (j < 16) cp16(smem_u32(&sK[slot][(j - 8) * 4]),  row + kcol + (j - 8) * 4);
        else if (j < 32) cp16(smem_u32(&sV[slot][(j - 16) * 4]), row + vcol + (j - 16) * 4);
    };
    prefetch1(0); cp_commit();
    prefetch1(1); cp_commit();
    prefetch1(2); cp_commit();

    for (int t = 0; t < T_; t++) {
        if      (t + 2 < T_) cp_wait<2>();
        else if (t + 1 < T_) cp_wait<1>();
        else                 cp_wait<0>();
        __syncthreads();
        if (t + 3 < T_) { prefetch1(t + 3); cp_commit(); }
        const int slot = t & 3;
        const float v = sV[slot][j];
        float o0 = 0.f, o1 = 0.f, o2 = 0.f, o3 = 0.f;
        #pragma unroll
        for (int i = 0; i < NST_; i += 4) {
            hst[i]   = fmaf(alpha[i],   hst[i],   sK[slot][i]   * v); o0 = fmaf(sQ[slot][i],   hst[i],   o0);
            hst[i+1] = fmaf(alpha[i+1], hst[i+1], sK[slot][i+1] * v); o1 = fmaf(sQ[slot][i+1], hst[i+1], o1);
            hst[i+2] = fmaf(alpha[i+2], hst[i+2], sK[slot][i+2] * v); o2 = fmaf(sQ[slot][i+2], hst[i+2], o2);
            hst[i+3] = fmaf(alpha[i+3], hst[i+3], sK[slot][i+3] * v); o3 = fmaf(sQ[slot][i+3], hst[i+3], o3);
        }
        obuf[t][j] = (o0 + o1) + (o2 + o3);
        if (j < NST_) qbuf[t][j] = sQ[slot][j];
    }
    __syncthreads();

    // ---- publish local end state (not needed for last chunk) ----
    if (c < P_ - 1) {
        float* dst = st + (((size_t)bh * P_ + c) * NST_) * DH_ + j;
        #pragma unroll
        for (int i = 0; i < NST_; i++) dst[i * DH_] = hst[i];
        __threadfence();
        __syncthreads();
        if (j == 0) atomicExch(&flags[bh * P_ + c], 1);
    }

    // ---- pass 2 G prefetches (independent of lookback -> issue first) ----
    auto prefetch2 = [&](int t) {
        const float* row = rows + (size_t)t * 4096;
        const int slot = t & 3;
        if (j < 16) cp16(smem_u32(&sG[slot][j * 4]), row + gcol + j * 4);
    };
    prefetch2(0); cp_commit();
    prefetch2(1); cp_commit();
    prefetch2(2); cp_commit();

    // ---- lookback: Hin = sum_d aT^(c-1-d) * st_d ----
    float hp[NST_];
    #pragma unroll
    for (int i = 0; i < NST_; i++) hp[i] = 0.f;
    if (c > 0) {
        float aT[NST_];
        #pragma unroll
        for (int i = 0; i < NST_; i++) {
            float a2 = alpha[i];
            #pragma unroll
            for (int q = 0; q < 6; q++) a2 *= a2;   // alpha^64
            aT[i] = a2;
        }
        for (int d = 0; d < c; d++) {
            const int* fp = &flags[bh * P_ + d];
            while (ld_acquire(fp) == 0) { }
            const float* src = st + (((size_t)bh * P_ + d) * NST_) * DH_ + j;
            #pragma unroll
            for (int i = 0; i < NST_; i++)
                hp[i] = fmaf(aT[i], hp[i], src[i * DH_]);
        }
    }

    // ---- pass 2: propagate Hin, correct, gate, write ----
    __nv_bfloat16* oh = Ohi + (size_t)m0 * D_ + h * DH_ + j;
    __nv_bfloat16* ol = Olo + (size_t)m0 * D_ + h * DH_ + j;

    if (c > 0) {
        for (int t = 0; t < T_; t++) {
            if      (t + 2 < T_) cp_wait<2>();
            else if (t + 1 < T_) cp_wait<1>();
            else                 cp_wait<0>();
            __syncthreads();
            if (t + 3 < T_) { prefetch2(t + 3); cp_commit(); }
            const int slot = t & 3;
            float c0 = 0.f, c1 = 0.f, c2 = 0.f, c3 = 0.f;
            #pragma unroll
            for (int i = 0; i < NST_; i += 4) {
                hp[i]   *= alpha[i];   c0 = fmaf(qbuf[t][i],   hp[i],   c0);
                hp[i+1] *= alpha[i+1]; c1 = fmaf(qbuf[t][i+1], hp[i+1], c1);
                hp[i+2] *= alpha[i+2]; c2 = fmaf(qbuf[t][i+2], hp[i+2], c2);
                hp[i+3] *= alpha[i+3]; c3 = fmaf(qbuf[t][i+3], hp[i+3], c3);
            }
            const float o = obuf[t][j] + ((c0 + c1) + (c2 + c3));
            const float gg = sG[slot][j];
            const float ov = o * gg / (1.f + expf(-gg));
            __nv_bfloat16 hh, ll;
            split2(ov, hh, ll);
            *oh = hh; *ol = ll;
            oh += D_; ol += D_;
        }
    } else {
        // c == 0: Hin == 0, correction is identically zero -> gate only.
        for (int t = 0; t < T_; t++) {
            if      (t + 2 < T_) cp_wait<2>();
            else if (t + 1 < T_) cp_wait<1>();
            else                 cp_wait<0>();
            __syncthreads();
            if (t + 3 < T_) { prefetch2(t + 3); cp_commit(); }
            const int slot = t & 3;
            const float o = obuf[t][j];
            const float gg = sG[slot][j];
            const float ov = o * gg / (1.f + expf(-gg));
            __nv_bfloat16 hh, ll;
            split2(ov, hh, ll);
            *oh = hh; *ol = ll;
            oh += D_; ol += D_;
        }
    }
}

// ---------------- launch ----------------
extern "C" void kernel_launch(void* const* d_in, const int* in_sizes, int n_in,
                              void* d_out, int out_size)
{
    const int*   tokens = (const int*)  d_in[0];
    const float* emb    = (const float*)d_in[1];
    const float* pos    = (const float*)d_in[2];
    const float* ln_g   = (const float*)d_in[3];
    const float* ln_b   = (const float*)d_in[4];
    const float* wq     = (const float*)d_in[5];
    const float* bq     = (const float*)d_in[6];
    const float* wk     = (const float*)d_in[7];
    const float* bk     = (const float*)d_in[8];
    const float* wv     = (const float*)d_in[9];
    const float* bv     = (const float*)d_in[10];
    const float* wg     = (const float*)d_in[11];
    const float* bg     = (const float*)d_in[12];
    const float* wo     = (const float*)d_in[13];
    const float* bo     = (const float*)d_in[14];
    const float* alogit = (const float*)d_in[15];
    const float* fn_g   = (const float*)d_in[16];
    const float* fn_b   = (const float*)d_in[17];
    const float* head_w = (const float*)d_in[18];
    const float* head_b = (const float*)d_in[19];
    float*       out    = (float*)d_out;

    float *px, *pqkvg, *pst, *pbcat;
    int* pflags;
    __nv_bfloat16 *pxnh, *pxnl, *poh, *pol;
    __nv_bfloat16 *wch, *wcl, *woh, *wol, *hwh, *hwl;
    cudaGetSymbolAddress((void**)&px,    g_x);
    cudaGetSymbolAddress((void**)&pqkvg, g_qkvg);
    cudaGetSymbolAddress((void**)&pst,   g_st);
    cudaGetSymbolAddress((void**)&pflags,g_flags);
    cudaGetSymbolAddress((void**)&pbcat, g_bcat);
    cudaGetSymbolAddress((void**)&pxnh,  g_xn_hi);
    cudaGetSymbolAddress((void**)&pxnl,  g_xn_lo);
    cudaGetSymbolAddress((void**)&poh,   g_o_hi);
    cudaGetSymbolAddress((void**)&pol,   g_o_lo);
    cudaGetSymbolAddress((void**)&wch,   g_wc_hi); cudaGetSymbolAddress((void**)&wcl, g_wc_lo);
    cudaGetSymbolAddress((void**)&woh,   g_wo_hi); cudaGetSymbolAddress((void**)&wol, g_wo_lo);
    cudaGetSymbolAddress((void**)&hwh,   g_hw_hi); cudaGetSymbolAddress((void**)&hwl, g_hw_lo);

    constexpr int SMEM_128 = 3 * (128 + 128) * 128;   // 98304
    constexpr int SMEM_32  = 3 * (32  + 128) * 128;   // 61440
    cudaFuncSetAttribute((gemm_mma<128, false>), cudaFuncAttributeMaxDynamicSharedMemorySize, SMEM_128);
    cudaFuncSetAttribute((gemm_mma<128, true >), cudaFuncAttributeMaxDynamicSharedMemorySize, SMEM_128);
    cudaFuncSetAttribute((gemm_mma<32,  false>), cudaFuncAttributeMaxDynamicSharedMemorySize, SMEM_32);

    // launch order: harness prepends 2; ncu -s 5 profiles overall #5 = our #3
    // = the first scan_fused.
    constexpr int CVT_TOT = (L_*4*D_*D_ + L_*D_*D_ + VOCAB_*D_ + L_*4*D_ + M_*D_) / 4
                            + L_ * B_ * H_ * P_;
    cvt_all<<<(CVT_TOT + 255) / 256, 256>>>(wq, wk, wv, wg, wo, head_w,
                                            bq, bk, bv, bg, tokens, emb, pos,
                                            wch, wcl, woh, wol, hwh, hwl,
                                            pbcat, px, pflags);                   // 0

    const dim3 qkvg_grid(4 * D_ / 128, M_ / 128);   // (32, 32) = 1024 CTAs
    const dim3 wo_grid(D_ / 128, M_ / 128);         // (8, 32)  = 256 CTAs
    const dim3 head_grid(1, M_ / 32);               // (1, 128) = 128 CTAs
    const size_t PIECE = (size_t)D_ * D_;

    for (int l = 0; l < L_; l++) {
        const size_t wOff = (size_t)l * PIECE;
        const float* alog = alogit + (size_t)l * H_ * NST_;

        ln_bf16_kernel<<<M_, 256>>>(px, ln_g + l * D_, ln_b + l * D_, pxnh, pxnl); // 1

        gemm_mma<128, false><<<qkvg_grid, 256, SMEM_128>>>(pxnh, pxnl,             // 2
            wch + (size_t)l * 4 * PIECE, wcl + (size_t)l * 4 * PIECE,
            pbcat + l * 4 * D_, nullptr, pqkvg, 4 * D_);

        scan_fused<<<dim3(B_ * H_, P_), 64>>>(pqkvg, alog, pst,                    // 3 <- profiled
            pflags + l * B_ * H_ * P_, poh, pol);

        gemm_mma<128, true><<<wo_grid, 256, SMEM_128>>>(poh, pol, woh + wOff, wol + wOff,
                                                        bo + l * D_, px, px, D_);
    }

    ln_bf16_kernel<<<M_, 256>>>(px, fn_g, fn_b, pxnh, pxnl);
    gemm_mma<32, false><<<head_grid, 256, SMEM_32>>>(pxnh, pxnl, hwh, hwl,
                                                     head_b, nullptr, out, VOCAB_);
}